// round 15
// baseline (speedup 1.0000x reference)
#include <cuda_runtime.h>

// ---------------------------------------------------------------------------
// Fused pre-MLP(tanh) -> complex FIR(32) -> post-MLP(relu), one HBM pass.
// R14: R4 block-tile structure + f32x2-paired pre-MLP + float4-packed FIR
//      weights (1 LDS.128/tap) + paired stage-C MLP. Single kernel.
// ---------------------------------------------------------------------------

#define FILTER_LEN 32
#define HALO       (FILTER_LEN - 1)          // 31
#define W_IN       262144
#define W_OUT      (W_IN - HALO)             // 262113
#define BATCH      16
#define THREADS    128
#define T_OUT      8
#define TILE       (THREADS * T_OUT)         // 1024
#define TILES_ROW  ((W_OUT + TILE - 1) / TILE)  // 256
#define NLOAD      (TILE + HALO)             // 1055
#define PAD(i)     ((i) + ((i) >> 3))
#define SPAD       (PAD(NLOAD - 1) + 1)

#define OUT_SCALE  0.17782794100389228f      // sqrt(10^(-15/10))

typedef unsigned long long u64;

// ---- packed f32x2 helpers (Blackwell FFMA2 path) ----
__device__ __forceinline__ u64 pk2(float lo, float hi) {
    u64 r;
    asm("mov.b64 %0, {%1, %2};" : "=l"(r) : "f"(lo), "f"(hi));
    return r;
}
__device__ __forceinline__ void upk2(u64 v, float& lo, float& hi) {
    asm("mov.b64 {%0, %1}, %2;" : "=f"(lo), "=f"(hi) : "l"(v));
}
__device__ __forceinline__ u64 ffma2(u64 a, u64 b, u64 c) {
    u64 d;
    asm("fma.rn.f32x2 %0, %1, %2, %3;" : "=l"(d) : "l"(a), "l"(b), "l"(c));
    return d;
}
__device__ __forceinline__ u64 fmul2(u64 a, u64 b) {
    u64 d;
    asm("mul.rn.f32x2 %0, %1, %2;" : "=l"(d) : "l"(a), "l"(b));
    return d;
}
__device__ __forceinline__ float tanh_approx(float x) {
    float y;
    asm("tanh.approx.f32 %0, %1;" : "=f"(y) : "f"(x));
    return y;
}
__device__ __forceinline__ u64 lds64(const float2* p) {
    return *reinterpret_cast<const u64*>(p);
}

__global__ void __launch_bounds__(THREADS, 8)
hammer_wiener_kernel(const float* __restrict__ x_real,
                     const float* __restrict__ x_imag,
                     const float* __restrict__ w1_pre,
                     const float* __restrict__ w2_pre,
                     const float* __restrict__ w_fir_r,
                     const float* __restrict__ w_fir_i,
                     const float* __restrict__ w1_post,
                     const float* __restrict__ b1_post,
                     const float* __restrict__ w2_post,
                     const float* __restrict__ b2_post,
                     float2* __restrict__ out) {
    __shared__ float2 s_xh[SPAD];            // packed (xh_r, xh_i), padded
    __shared__ float4 s_wpk[FILTER_LEN];     // (wr, wr, wi, wi) per tap
    __shared__ float2 s_w1a2[8];             // (w1_pre, w1_pre)
    __shared__ float2 s_w2a2[8];             // (w2_pre, w2_pre)
    __shared__ float2 s_w1b2[8];             // (w1_post, w1_post)
    __shared__ float2 s_b1b2[8];
    __shared__ float2 s_w2b2[8];
    __shared__ float  s_b2b;

    const int tid   = threadIdx.x;
    const int b     = blockIdx.y;
    const int tile0 = blockIdx.x * TILE;

    // ---- params -> shared ----
    if (tid < FILTER_LEN) {
        float wr = w_fir_r[tid];
        float wi = w_fir_i[tid];
        s_wpk[tid] = make_float4(wr, wr, wi, wi);
    }
    if (tid >= 32 && tid < 40) {
        int j = tid - 32;
        float a1 = w1_pre[j],  a2 = w2_pre[j];
        float p1 = w1_post[j], pb = b1_post[j], p2 = w2_post[j];
        s_w1a2[j] = make_float2(a1, a1);
        s_w2a2[j] = make_float2(a2, a2);
        s_w1b2[j] = make_float2(p1, p1);
        s_b1b2[j] = make_float2(pb, pb);
        s_w2b2[j] = make_float2(p2, p2);
    }
    if (tid == 40) s_b2b = b2_post[0];
    __syncthreads();

    // ---- stage A: pre nonlinearity (f32x2-paired MLP) -> shared window ----
    const float* __restrict__ xr_row = x_real + (size_t)b * W_IN;
    const float* __restrict__ xi_row = x_imag + (size_t)b * W_IN;

#pragma unroll
    for (int it = 0; it < TILE / (4 * THREADS); it++) {   // 2 iterations
        int t = tid + it * THREADS;                       // float4 slot
        float4 r4 = *reinterpret_cast<const float4*>(xr_row + tile0 + 4 * t);
        float4 i4 = *reinterpret_cast<const float4*>(xi_row + tile0 + 4 * t);
        int p0 = PAD(4 * t);                              // 4-group within one 8-block
        float rr[4] = {r4.x, r4.y, r4.z, r4.w};
        float ii[4] = {i4.x, i4.y, i4.z, i4.w};
#pragma unroll
        for (int h = 0; h < 2; h++) {                     // two sample-pairs
            float ra = rr[2 * h],     rb = rr[2 * h + 1];
            float ia = ii[2 * h],     ib = ii[2 * h + 1];
            u64 rp = pk2(ra, rb);
            u64 ip = pk2(ia, ib);
            u64 m2p = ffma2(rp, rp, fmul2(ip, ip));
            float m2a, m2b;
            upk2(m2p, m2a, m2b);
            float inva = rsqrtf(m2a);
            float invb = rsqrtf(m2b);
            bool  nza  = (m2a > 0.0f);
            bool  nzb  = (m2b > 0.0f);
            u64 magp = fmul2(m2p, pk2(nza ? inva : 0.0f, nzb ? invb : 0.0f));
            u64 accp = 0ULL;
#pragma unroll
            for (int j = 0; j < 8; j++) {
                u64 arg = fmul2(magp, lds64(&s_w1a2[j]));
                float aa, ab;
                upk2(arg, aa, ab);
                float ta = tanh_approx(aa);
                float tb = tanh_approx(ab);
                accp = ffma2(pk2(ta, tb), lds64(&s_w2a2[j]), accp);
            }
            float acca, accb;
            upk2(accp, acca, accb);
            float sca = nza ? acca * inva : 0.0f;         // m / mag
            float scb = nzb ? accb * invb : 0.0f;
            *reinterpret_cast<u64*>(&s_xh[p0 + 2 * h])     = fmul2(pk2(sca, sca), pk2(ra, ia));
            *reinterpret_cast<u64*>(&s_xh[p0 + 2 * h + 1]) = fmul2(pk2(scb, scb), pk2(rb, ib));
        }
    }
    // halo: 31 scalar elements, guarded
    if (tid < HALO) {
        int i = TILE + tid;
        int g = tile0 + i;
        float r = 0.0f, im = 0.0f;
        if (g < W_IN) { r = xr_row[g]; im = xi_row[g]; }
        float m2  = fmaf(r, r, im * im);
        float inv = rsqrtf(m2);
        bool  nz  = (m2 > 0.0f);
        float mag = nz ? m2 * inv : 0.0f;
        float acc = 0.0f;
#pragma unroll
        for (int j = 0; j < 8; j++) {
            float2 w1 = s_w1a2[j];
            float2 w2 = s_w2a2[j];
            acc = fmaf(tanh_approx(mag * w1.x), w2.x, acc);
        }
        float sc = nz ? acc * inv : 0.0f;
        s_xh[PAD(i)] = make_float2(sc * r, sc * im);
    }
    __syncthreads();

    // ---- stage B: 32-tap complex FIR, ring-buffer window ----
    const int base = tid * T_OUT;

    u64 Wd[8];
#pragma unroll
    for (int i = 0; i < 8; i++) Wd[i] = lds64(&s_xh[PAD(base + i)]);

    u64 acc1[T_OUT], acc2[T_OUT];
#pragma unroll
    for (int j = 0; j < T_OUT; j++) { acc1[j] = 0ULL; acc2[j] = 0ULL; }

#pragma unroll
    for (int k = 0; k < FILTER_LEN; k++) {
        ulonglong2 wv = *reinterpret_cast<const ulonglong2*>(&s_wpk[k]);  // LDS.128
        u64 wrb = wv.x;                      // (wr, wr)
        u64 wib = wv.y;                      // (wi, wi)
#pragma unroll
        for (int j = 0; j < T_OUT; j++) {
            u64 a = Wd[(k + j) & 7];
            acc1[j] = ffma2(wrb, a, acc1[j]);
            acc2[j] = ffma2(wib, a, acc2[j]);
        }
        if (k < FILTER_LEN - 1)
            Wd[k & 7] = lds64(&s_xh[PAD(base + k + 8)]);
    }

    // ---- stage C: post nonlinearity (paired f32x2) + store ----
    const size_t out_base = (size_t)b * W_OUT;
    const int    n0       = tile0 + base;
    const float  b2b      = s_b2b;
#pragma unroll
    for (int j = 0; j < T_OUT; j += 2) {
        float a1lo, a1hi, a2lo, a2hi;
        upk2(acc1[j], a1lo, a1hi);
        upk2(acc2[j], a2lo, a2hi);
        float zr0 = a1lo - a2hi;
        float zi0 = a1hi + a2lo;
        upk2(acc1[j + 1], a1lo, a1hi);
        upk2(acc2[j + 1], a2lo, a2hi);
        float zr1 = a1lo - a2hi;
        float zi1 = a1hi + a2lo;

        float m20  = fmaf(zr0, zr0, zi0 * zi0);
        float m21  = fmaf(zr1, zr1, zi1 * zi1);
        float inv0 = rsqrtf(m20);
        float inv1 = rsqrtf(m21);
        bool  nz0  = (m20 > 0.0f);
        bool  nz1  = (m21 > 0.0f);
        float zg0  = nz0 ? m20 * inv0 : 0.0f;
        float zg1  = nz1 ? m21 * inv1 : 0.0f;

        u64 zm2 = pk2(zg0, zg1);
        u64 acc = pk2(b2b, b2b);
#pragma unroll
        for (int f = 0; f < 8; f++) {
            u64 g2 = ffma2(zm2, lds64(&s_w1b2[f]), lds64(&s_b1b2[f]));
            float glo, ghi;
            upk2(g2, glo, ghi);
            glo = fmaxf(glo, 0.0f);
            ghi = fmaxf(ghi, 0.0f);
            acc = ffma2(pk2(glo, ghi), lds64(&s_w2b2[f]), acc);
        }
        float zm0, zm1;
        upk2(acc, zm0, zm1);
        float sm0 = OUT_SCALE * zm0;
        float sm1 = OUT_SCALE * zm1;

        float t0 = sm0 * inv0;               // sm / |z|
        float t1 = sm1 * inv1;
        float yr0 = nz0 ? t0 * zr0 : sm0;    // cos(atan2(0,0)) = 1
        float yi0 = nz0 ? t0 * zi0 : 0.0f;
        float yr1 = nz1 ? t1 * zr1 : sm1;
        float yi1 = nz1 ? t1 * zi1 : 0.0f;

        int n = n0 + j;
        if (n < W_OUT)     out[out_base + n]     = make_float2(yr0, yi0);
        if (n + 1 < W_OUT) out[out_base + n + 1] = make_float2(yr1, yi1);
    }
}

extern "C" void kernel_launch(void* const* d_in, const int* in_sizes, int n_in,
                              void* d_out, int out_size) {
    (void)in_sizes; (void)n_in; (void)out_size;
    const float* x_real   = (const float*)d_in[0];
    const float* x_imag   = (const float*)d_in[1];
    const float* w1_pre   = (const float*)d_in[2];
    const float* w2_pre   = (const float*)d_in[3];
    const float* w_fir_r  = (const float*)d_in[4];
    const float* w_fir_i  = (const float*)d_in[5];
    const float* w1_post  = (const float*)d_in[6];
    const float* b1_post  = (const float*)d_in[7];
    const float* w2_post  = (const float*)d_in[8];
    const float* b2_post  = (const float*)d_in[9];

    dim3 grid(TILES_ROW, BATCH);
    hammer_wiener_kernel<<<grid, THREADS>>>(
        x_real, x_imag, w1_pre, w2_pre, w_fir_r, w_fir_i,
        w1_post, b1_post, w2_post, b2_post, (float2*)d_out);
}